// round 9
// baseline (speedup 1.0000x reference)
#include <cuda_runtime.h>

typedef unsigned long long ull;

#define B_   4
#define C_   64
#define H_   96
#define W_   96
#define DD   8
#define HW   (H_*W_)          // 9216
#define HWD  (H_*W_*DD)       // 73728
#define NIDX 243

#define PX   32
#define PT   8
#define CCH  8
#define NST  72      // 9 i-shifts * 8 channel chunks
#define F1COL 36     // stride/4 odd -> perfect 4-phase LDS.128
#define F2COL 44
#define F1W  (CCH*8*F1COL)     // 2304 words
#define F2W  (CCH*10*F2COL)    // 3520 words
#define SMEM_WORDS (2*F1W + 2*F2W)
#define SMEM_BYTES (SMEM_WORDS*4)   // 46592 B -> 4 blocks/SM

__device__ float g_m1[B_*HW];
__device__ float g_m2[B_*HW];

__device__ __forceinline__ void fma2(ull &d, ull a, ull b) {
    asm("fma.rn.f32x2 %0, %1, %2, %0;" : "+l"(d) : "l"(a), "l"(b));
}
__device__ __forceinline__ ull mul2(ull a, ull b) {
    ull d; asm("mul.rn.f32x2 %0, %1, %2;" : "=l"(d) : "l"(a), "l"(b)); return d;
}
__device__ __forceinline__ ull pack2(float lo, float hi) {
    ull r; asm("mov.b64 %0, {%1, %2};" : "=l"(r) : "f"(lo), "f"(hi)); return r;
}
__device__ __forceinline__ void unpack2(ull v, float &lo, float &hi) {
    asm("mov.b64 {%0, %1}, %2;" : "=f"(lo), "=f"(hi) : "l"(v));
}

// ---------------------------------------------------------------------------
// Producer helpers. f2 slots: 672 = 8cl * 84 (42 cols * 2 z-quads); cl via
// exact mul-shift (idx*781)>>16 == idx/84 for idx<672 (verified bound).
// f1 slots: 512 = 8c * 64.
// ---------------------------------------------------------------------------
__device__ __forceinline__ void f2slot(int idx, int xb, int &cl, int &col, int &q, int &gx) {
    cl  = (idx * 781) >> 16;
    int r = idx - cl * 84;
    col = r >> 1;
    q   = r & 1;
    gx  = xb - 4 + col;
}

__device__ __forceinline__ void ld_f2(const float* s2, bool vrow, int lane, int t0,
                                      int xb, float4* dst) {
    #pragma unroll
    for (int u = 0; u < 7; u++) {
        int cl, col, q, gx;
        f2slot(lane + (t0 + u) * 32, xb, cl, col, q, gx);
        float4 v = make_float4(0.f, 0.f, 0.f, 0.f);
        if (vrow && gx >= 0 && gx < W_)
            v = *(const float4*)(s2 + (size_t)cl * HWD + gx * DD + q * 4);
        dst[u] = v;
    }
}
__device__ __forceinline__ void st_f2(float* f2d, int lane, int t0, int xb,
                                      const float4* src) {
    #pragma unroll
    for (int u = 0; u < 7; u++) {
        int cl, col, q, gx;
        f2slot(lane + (t0 + u) * 32, xb, cl, col, q, gx);
        int wb = (cl * 10 + 1 + q * 4) * F2COL + col;
        f2d[wb]           = src[u].x;
        f2d[wb +   F2COL] = src[u].y;
        f2d[wb + 2*F2COL] = src[u].z;
        f2d[wb + 3*F2COL] = src[u].w;
    }
}
__device__ __forceinline__ void ld_f1(const float* s1, int lane, int t0, float4* dst) {
    #pragma unroll
    for (int u = 0; u < 8; u++) {
        int idx = lane + (t0 + u) * 32;
        int c = idx >> 6, r = idx & 63, col = r >> 1, q = r & 1;
        dst[u] = *(const float4*)(s1 + (size_t)c * HWD + col * DD + q * 4);
    }
}
__device__ __forceinline__ void st_f1(float* f1d, int lane, int t0, const float4* src) {
    #pragma unroll
    for (int u = 0; u < 8; u++) {
        int idx = lane + (t0 + u) * 32;
        int c = idx >> 6, r = idx & 63, col = r >> 1, q = r & 1;
        int wb = (c * 8 + q * 4) * F1COL + col;
        f1d[wb]           = src[u].x;
        f1d[wb +   F1COL] = src[u].y;
        f1d[wb + 2*F1COL] = src[u].z;
        f1d[wb + 3*F1COL] = src[u].w;
    }
}

// full stage fill by the producer warp (pipelined batches, <=2 live)
__device__ __forceinline__ void fill_stage_prod(
    float* __restrict__ f1d, float* __restrict__ f2d,
    const float* __restrict__ f1g, const float* __restrict__ f2g,
    int b, int y, int xb, int i, int cc, int lane)
{
    const int cbase = cc * CCH;
    const int yr = y + i - 4;
    const bool vrow = (yr >= 0) && (yr < H_);
    const float* s2 = f2g + ((size_t)(b*C_ + cbase))*HWD
                    + (size_t)(vrow ? yr : 0) * (W_*DD);
    const float* s1 = f1g + ((size_t)(b*C_ + cbase))*HWD
                    + ((size_t)y*W_ + xb) * DD;

    float4 A[7], Bv[7], Cv[7], D[8], E[8];
    ld_f2(s2, vrow, lane, 0,  xb, A);
    ld_f2(s2, vrow, lane, 7,  xb, Bv);
    st_f2(f2d, lane, 0,  xb, A);
    ld_f2(s2, vrow, lane, 14, xb, Cv);
    st_f2(f2d, lane, 7,  xb, Bv);
    ld_f1(s1, lane, 0, D);
    st_f2(f2d, lane, 14, xb, Cv);
    ld_f1(s1, lane, 8, E);
    st_f1(f1d, lane, 0, D);
    st_f1(f1d, lane, 8, E);
}

// ---------------------------------------------------------------------------
// 4 channels of correlation (ull-native LDS.128 pairs; only 7 odd packs).
// ---------------------------------------------------------------------------
__device__ __forceinline__ void compute4(
    const float* __restrict__ f1s, const float* __restrict__ f2s,
    int clbase, int z, int zi, int lx0, ull acc[4][9])
{
    #pragma unroll
    for (int cu = 0; cu < 4; cu++) {
        const int cl = clbase + cu;
        const ulonglong2* p1 = (const ulonglong2*)(f1s + (cl*8 + z)*F1COL + lx0);
        ulonglong2 V0 = p1[0], V1 = p1[1];
        ull vp[4]; vp[0]=V0.x; vp[1]=V0.y; vp[2]=V1.x; vp[3]=V1.y;

        const ulonglong2* p2 = (const ulonglong2*)(f2s + (cl*10 + zi)*F2COL + lx0);
        ulonglong2 E0 = p2[0], E1 = p2[1], E2 = p2[2], E3 = p2[3];
        ull e[8];
        e[0]=E0.x; e[1]=E0.y; e[2]=E1.x; e[3]=E1.y;
        e[4]=E2.x; e[5]=E2.y; e[6]=E3.x; e[7]=E3.y;

        ull o[7];
        #pragma unroll
        for (int m = 0; m < 7; m++) {
            float l0, h0, l1, h1;
            unpack2(e[m],   l0, h0);
            unpack2(e[m+1], l1, h1);
            o[m] = pack2(h0, l1);
        }

        #pragma unroll
        for (int xp = 0; xp < 4; xp++) {
            #pragma unroll
            for (int j = 0; j < 9; j++) {
                ull tp = (j & 1) ? o[xp + ((j-1)>>1)] : e[xp + (j>>1)];
                fma2(acc[xp][j], vp[xp], tp);
            }
        }
    }
}

// ---------------------------------------------------------------------------
// Warp-specialized cost + mask kernel. 128 threads = 4 warps; producer warp
// index rotates with blockIdx.x so producers spread across SMSPs (wid%4 law).
// Compute warps (k=0..2): pure LDS+FMA+stores. Producer: all fills.
// ---------------------------------------------------------------------------
__global__ void __launch_bounds__(128, 4)
cost_kernel(const float* __restrict__ f1g, const float* __restrict__ f2g,
            float* __restrict__ out, float* __restrict__ omask)
{
    extern __shared__ float sm[];
    float* f1b0 = sm;
    float* f1b1 = sm + F1W;
    float* f2b0 = sm + 2*F1W;
    float* f2b1 = sm + 2*F1W + F2W;

    const int tid  = threadIdx.x;
    const int wid  = tid >> 5;
    const int lane = tid & 31;
    const int xb   = blockIdx.x * PX;
    const int y    = blockIdx.y;
    const int b    = blockIdx.z;

    const int  pwid     = blockIdx.x & 3;       // rotating producer warp
    const bool producer = (wid == pwid);
    const int  k        = wid - (wid > pwid ? 1 : 0);   // 0..2 for compute warps

    const int txg = lane & 3;
    const int z   = lane >> 2;
    const int lx0 = txg * PT;
    const int zi  = z + k;

    // zero the z-pad planes of both f2 buffers (all threads, once)
    for (int n = tid; n < 2*CCH*2*F2COL; n += 128) {
        int p   = n / (CCH*2*F2COL);
        int r   = n - p*(CCH*2*F2COL);
        int cl  = r / (2*F2COL);
        int r2  = r - cl*(2*F2COL);
        int zp  = (r2 >= F2COL) ? 9 : 0;
        int col = (r2 >= F2COL) ? (r2 - F2COL) : r2;
        (p ? f2b1 : f2b0)[(cl*10 + zp)*F2COL + col] = 0.f;
    }
    __syncthreads();

    if (producer)
        fill_stage_prod(f1b0, f2b0, f1g, f2g, b, y, xb, 0, 0, lane);

    const bool zedge = (zi == 0) || (zi == 9);
    ull acc[4][9];

    for (int s = 0; s < NST; s++) {
        const int par = s & 1;
        __syncthreads();   // buf[par] filled; prior use of buf[par^1] done

        if (producer) {
            if (s + 1 < NST) {
                const int sn = s + 1;
                fill_stage_prod(par ? f1b0 : f1b1, par ? f2b0 : f2b1,
                                f1g, f2g, b, y, xb, sn >> 3, sn & 7, lane);
            }
            continue;
        }

        const float* f1s = par ? f1b1 : f1b0;
        const float* f2s = par ? f2b1 : f2b0;

        const int i  = s >> 3;
        const int cc = s & 7;

        if (cc == 0) {
            #pragma unroll
            for (int xp = 0; xp < 4; xp++)
                #pragma unroll
                for (int j = 0; j < 9; j++) acc[xp][j] = 0ull;
        }

        compute4(f1s, f2s, 0, z, zi, lx0, acc);
        compute4(f1s, f2s, 4, z, zi, lx0, acc);

        if (cc == 7) {
            const ull scc = pack2(1.0f/64.0f, 1.0f/64.0f);
            long obase = ((long)(b*NIDX + k*81 + i*9) * HW
                          + (long)y*W_ + xb + lx0) * DD + z;
            #pragma unroll
            for (int xp = 0; xp < 4; xp++) {
                #pragma unroll
                for (int j = 0; j < 9; j++) {
                    float s0f, s1f; unpack2(mul2(acc[xp][j], scc), s0f, s1f);
                    out[obase + (long)j*HWD + (2*xp  )*DD] = s0f;
                    out[obase + (long)j*HWD + (2*xp+1)*DD] = s1f;
                }
            }
            // fused mask output
            const int yr = y + i - 4;
            const bool vrow = (yr >= 0) && (yr < H_);
            float m1x[PT];
            {
                const float* m1p = g_m1 + b*HW + y*W_ + xb + lx0;
                float4 a = *(const float4*)(m1p);
                float4 c = *(const float4*)(m1p + 4);
                m1x[0]=a.x; m1x[1]=a.y; m1x[2]=a.z; m1x[3]=a.w;
                m1x[4]=c.x; m1x[5]=c.y; m1x[6]=c.z; m1x[7]=c.w;
            }
            float m2w[16];
            #pragma unroll
            for (int n = 0; n < 16; n++) {
                int gxr = xb + lx0 - 4 + n;
                m2w[n] = (vrow && gxr >= 0 && gxr < W_)
                           ? __ldg(g_m2 + b*HW + yr*W_ + gxr) : 1.0f;
            }
            #pragma unroll
            for (int xi = 0; xi < PT; xi++) {
                #pragma unroll
                for (int j = 0; j < 9; j++) {
                    float mv = zedge ? m1x[xi] : (m1x[xi] * m2w[xi + j]);
                    omask[obase + (long)j*HWD + xi*DD] = mv;
                }
            }
        }
    }
}

// ---------------------------------------------------------------------------
__global__ void mask_sum_kernel(const float* __restrict__ a1,
                                const float* __restrict__ a2) {
    int n = blockIdx.x * blockDim.x + threadIdx.x;
    if (n >= B_*HW) return;
    const float4* p1 = (const float4*)(a1 + (size_t)n * DD);
    const float4* p2 = (const float4*)(a2 + (size_t)n * DD);
    float4 u = p1[0], v = p1[1];
    float s1 = u.x+u.y+u.z+u.w + v.x+v.y+v.z+v.w;
    u = p2[0]; v = p2[1];
    float s2 = u.x+u.y+u.z+u.w + v.x+v.y+v.z+v.w;
    g_m1[n] = fminf(fmaxf(s1, 0.f), 1.f);
    g_m2[n] = fminf(fmaxf(s2, 0.f), 1.f);
}

// ---------------------------------------------------------------------------
extern "C" void kernel_launch(void* const* d_in, const int* in_sizes, int n_in,
                              void* d_out, int out_size) {
    const float* f1 = (const float*)d_in[0];
    const float* a1 = (const float*)d_in[1];
    const float* f2 = (const float*)d_in[2];
    const float* a2 = (const float*)d_in[3];
    float* out      = (float*)d_out;
    float* out_mask = out + (long)B_ * NIDX * HWD;

    mask_sum_kernel<<<(B_*HW + 255) / 256, 256>>>(a1, a2);

    dim3 g(W_ / PX, H_, B_);
    cost_kernel<<<g, 128, SMEM_BYTES>>>(f1, f2, out, out_mask);
}

// round 10
// speedup vs baseline: 1.0952x; 1.0952x over previous
#include <cuda_runtime.h>

typedef unsigned long long ull;

#define B_   4
#define C_   64
#define H_   96
#define W_   96
#define DD   8
#define HW   (H_*W_)          // 9216
#define HWD  (H_*W_*DD)       // 73728
#define NIDX 243

#define PX   32
#define PT   8
#define CCH  8
#define NST  72      // 9 i-shifts * 8 channel chunks
#define F1COL 36     // stride/4 odd -> perfect 4-phase LDS.128
#define F2COL 44
#define F1W  (CCH*8*F1COL)     // 2304 words
#define F2W  (CCH*10*F2COL)    // 3520 words
#define SMEM_WORDS (2*F1W + 2*F2W)
#define SMEM_BYTES (SMEM_WORDS*4)   // 46592 B -> 3 blocks/SM fits easily

__device__ float g_m1[B_*HW];
__device__ float g_m2[B_*HW];

__device__ __forceinline__ void fma2(ull &d, ull a, ull b) {
    asm("fma.rn.f32x2 %0, %1, %2, %0;" : "+l"(d) : "l"(a), "l"(b));
}
__device__ __forceinline__ ull mul2(ull a, ull b) {
    ull d; asm("mul.rn.f32x2 %0, %1, %2;" : "=l"(d) : "l"(a), "l"(b)); return d;
}
__device__ __forceinline__ ull pack2(float lo, float hi) {
    ull r; asm("mov.b64 %0, {%1, %2};" : "=l"(r) : "f"(lo), "f"(hi)); return r;
}
__device__ __forceinline__ void unpack2(ull v, float &lo, float &hi) {
    asm("mov.b64 {%0, %1}, %2;" : "=f"(lo), "=f"(hi) : "l"(v));
}

// ---------------------------------------------------------------------------
// Producer helpers. f2: 672 slots = 8cl*84; cl = (idx*781)>>16 == idx/84 for
// idx<672. f1: 512 slots = 8c*64.
// ---------------------------------------------------------------------------
__device__ __forceinline__ void f2slot(int idx, int xb, int &cl, int &col, int &q, int &gx) {
    cl  = (idx * 781) >> 16;
    int r = idx - cl * 84;
    col = r >> 1;
    q   = r & 1;
    gx  = xb - 4 + col;
}

__device__ __forceinline__ void ld_f2(const float* s2, bool vrow, int lane, int t0,
                                      int xb, float4* dst) {
    #pragma unroll
    for (int u = 0; u < 7; u++) {
        int cl, col, q, gx;
        f2slot(lane + (t0 + u) * 32, xb, cl, col, q, gx);
        float4 v = make_float4(0.f, 0.f, 0.f, 0.f);
        if (vrow && gx >= 0 && gx < W_)
            v = *(const float4*)(s2 + (size_t)cl * HWD + gx * DD + q * 4);
        dst[u] = v;
    }
}
__device__ __forceinline__ void st_f2(float* f2d, int lane, int t0, int xb,
                                      const float4* src) {
    #pragma unroll
    for (int u = 0; u < 7; u++) {
        int cl, col, q, gx;
        f2slot(lane + (t0 + u) * 32, xb, cl, col, q, gx);
        int wb = (cl * 10 + 1 + q * 4) * F2COL + col;
        f2d[wb]           = src[u].x;
        f2d[wb +   F2COL] = src[u].y;
        f2d[wb + 2*F2COL] = src[u].z;
        f2d[wb + 3*F2COL] = src[u].w;
    }
}
__device__ __forceinline__ void ld_f1(const float* s1, int lane, int t0, float4* dst) {
    #pragma unroll
    for (int u = 0; u < 8; u++) {
        int idx = lane + (t0 + u) * 32;
        int c = idx >> 6, r = idx & 63, col = r >> 1, q = r & 1;
        dst[u] = *(const float4*)(s1 + (size_t)c * HWD + col * DD + q * 4);
    }
}
__device__ __forceinline__ void st_f1(float* f1d, int lane, int t0, const float4* src) {
    #pragma unroll
    for (int u = 0; u < 8; u++) {
        int idx = lane + (t0 + u) * 32;
        int c = idx >> 6, r = idx & 63, col = r >> 1, q = r & 1;
        int wb = (c * 8 + q * 4) * F1COL + col;
        f1d[wb]           = src[u].x;
        f1d[wb +   F1COL] = src[u].y;
        f1d[wb + 2*F1COL] = src[u].z;
        f1d[wb + 3*F1COL] = src[u].w;
    }
}

// full stage fill by the producer warp (pipelined batches, <=2 live)
__device__ __forceinline__ void fill_stage_prod(
    float* __restrict__ f1d, float* __restrict__ f2d,
    const float* __restrict__ f1g, const float* __restrict__ f2g,
    int b, int y, int xb, int i, int cc, int lane)
{
    const int cbase = cc * CCH;
    const int yr = y + i - 4;
    const bool vrow = (yr >= 0) && (yr < H_);
    const float* s2 = f2g + ((size_t)(b*C_ + cbase))*HWD
                    + (size_t)(vrow ? yr : 0) * (W_*DD);
    const float* s1 = f1g + ((size_t)(b*C_ + cbase))*HWD
                    + ((size_t)y*W_ + xb) * DD;

    float4 A[7], Bv[7], Cv[7], D[8], E[8];
    ld_f2(s2, vrow, lane, 0,  xb, A);
    ld_f2(s2, vrow, lane, 7,  xb, Bv);
    st_f2(f2d, lane, 0,  xb, A);
    ld_f2(s2, vrow, lane, 14, xb, Cv);
    st_f2(f2d, lane, 7,  xb, Bv);
    ld_f1(s1, lane, 0, D);
    st_f2(f2d, lane, 14, xb, Cv);
    ld_f1(s1, lane, 8, E);
    st_f1(f1d, lane, 0, D);
    st_f1(f1d, lane, 8, E);
}

// ---------------------------------------------------------------------------
// 4 channels of correlation (ull-native LDS.128 pairs; only 7 odd packs).
// ---------------------------------------------------------------------------
__device__ __forceinline__ void compute4(
    const float* __restrict__ f1s, const float* __restrict__ f2s,
    int clbase, int z, int zi, int lx0, ull acc[4][9])
{
    #pragma unroll
    for (int cu = 0; cu < 4; cu++) {
        const int cl = clbase + cu;
        const ulonglong2* p1 = (const ulonglong2*)(f1s + (cl*8 + z)*F1COL + lx0);
        ulonglong2 V0 = p1[0], V1 = p1[1];
        ull vp[4]; vp[0]=V0.x; vp[1]=V0.y; vp[2]=V1.x; vp[3]=V1.y;

        const ulonglong2* p2 = (const ulonglong2*)(f2s + (cl*10 + zi)*F2COL + lx0);
        ulonglong2 E0 = p2[0], E1 = p2[1], E2 = p2[2], E3 = p2[3];
        ull e[8];
        e[0]=E0.x; e[1]=E0.y; e[2]=E1.x; e[3]=E1.y;
        e[4]=E2.x; e[5]=E2.y; e[6]=E3.x; e[7]=E3.y;

        ull o[7];
        #pragma unroll
        for (int m = 0; m < 7; m++) {
            float l0, h0, l1, h1;
            unpack2(e[m],   l0, h0);
            unpack2(e[m+1], l1, h1);
            o[m] = pack2(h0, l1);
        }

        #pragma unroll
        for (int xp = 0; xp < 4; xp++) {
            #pragma unroll
            for (int j = 0; j < 9; j++) {
                ull tp = (j & 1) ? o[xp + ((j-1)>>1)] : e[xp + (j>>1)];
                fma2(acc[xp][j], vp[xp], tp);
            }
        }
    }
}

// ---------------------------------------------------------------------------
// Warp-specialized cost + mask kernel. 128 threads = 4 warps.
// wid 0..2 = compute (k = wid), wid 3 = producer. With wid%4 -> SMSP, all
// producer warps occupy SMSP 3 (previously idle with 96-thread blocks);
// SMSPs 0-2 carry 3 pure-compute warps each at 3 blocks/SM.
// launch_bounds(128,3): 170-reg budget -> no accumulator spills (R9's bug).
// ---------------------------------------------------------------------------
__global__ void __launch_bounds__(128, 3)
cost_kernel(const float* __restrict__ f1g, const float* __restrict__ f2g,
            float* __restrict__ out, float* __restrict__ omask)
{
    extern __shared__ float sm[];
    float* f1b0 = sm;
    float* f1b1 = sm + F1W;
    float* f2b0 = sm + 2*F1W;
    float* f2b1 = sm + 2*F1W + F2W;

    const int tid  = threadIdx.x;
    const int wid  = tid >> 5;
    const int lane = tid & 31;
    const int xb   = blockIdx.x * PX;
    const int y    = blockIdx.y;
    const int b    = blockIdx.z;

    const bool producer = (wid == 3);
    const int  k        = wid;            // 0..2 for compute warps

    const int txg = lane & 3;
    const int z   = lane >> 2;
    const int lx0 = txg * PT;
    const int zi  = z + k;

    // zero the z-pad planes of both f2 buffers (all threads, once)
    for (int n = tid; n < 2*CCH*2*F2COL; n += 128) {
        int p   = n / (CCH*2*F2COL);
        int r   = n - p*(CCH*2*F2COL);
        int cl  = r / (2*F2COL);
        int r2  = r - cl*(2*F2COL);
        int zp  = (r2 >= F2COL) ? 9 : 0;
        int col = (r2 >= F2COL) ? (r2 - F2COL) : r2;
        (p ? f2b1 : f2b0)[(cl*10 + zp)*F2COL + col] = 0.f;
    }
    __syncthreads();

    if (producer)
        fill_stage_prod(f1b0, f2b0, f1g, f2g, b, y, xb, 0, 0, lane);

    const bool zedge = (zi == 0) || (zi == 9);
    ull acc[4][9];

    for (int s = 0; s < NST; s++) {
        const int par = s & 1;
        __syncthreads();   // buf[par] filled; prior use of buf[par^1] done

        if (producer) {
            if (s + 1 < NST) {
                const int sn = s + 1;
                fill_stage_prod(par ? f1b0 : f1b1, par ? f2b0 : f2b1,
                                f1g, f2g, b, y, xb, sn >> 3, sn & 7, lane);
            }
            continue;
        }

        const float* f1s = par ? f1b1 : f1b0;
        const float* f2s = par ? f2b1 : f2b0;

        const int i  = s >> 3;
        const int cc = s & 7;

        if (cc == 0) {
            #pragma unroll
            for (int xp = 0; xp < 4; xp++)
                #pragma unroll
                for (int j = 0; j < 9; j++) acc[xp][j] = 0ull;
        }

        compute4(f1s, f2s, 0, z, zi, lx0, acc);
        compute4(f1s, f2s, 4, z, zi, lx0, acc);

        if (cc == 7) {
            const ull scc = pack2(1.0f/64.0f, 1.0f/64.0f);
            long obase = ((long)(b*NIDX + k*81 + i*9) * HW
                          + (long)y*W_ + xb + lx0) * DD + z;
            #pragma unroll
            for (int xp = 0; xp < 4; xp++) {
                #pragma unroll
                for (int j = 0; j < 9; j++) {
                    float s0f, s1f; unpack2(mul2(acc[xp][j], scc), s0f, s1f);
                    out[obase + (long)j*HWD + (2*xp  )*DD] = s0f;
                    out[obase + (long)j*HWD + (2*xp+1)*DD] = s1f;
                }
            }
            // fused mask output
            const int yr = y + i - 4;
            const bool vrow = (yr >= 0) && (yr < H_);
            float m1x[PT];
            {
                const float* m1p = g_m1 + b*HW + y*W_ + xb + lx0;
                float4 a = *(const float4*)(m1p);
                float4 c = *(const float4*)(m1p + 4);
                m1x[0]=a.x; m1x[1]=a.y; m1x[2]=a.z; m1x[3]=a.w;
                m1x[4]=c.x; m1x[5]=c.y; m1x[6]=c.z; m1x[7]=c.w;
            }
            float m2w[16];
            #pragma unroll
            for (int n = 0; n < 16; n++) {
                int gxr = xb + lx0 - 4 + n;
                m2w[n] = (vrow && gxr >= 0 && gxr < W_)
                           ? __ldg(g_m2 + b*HW + yr*W_ + gxr) : 1.0f;
            }
            #pragma unroll
            for (int xi = 0; xi < PT; xi++) {
                #pragma unroll
                for (int j = 0; j < 9; j++) {
                    float mv = zedge ? m1x[xi] : (m1x[xi] * m2w[xi + j]);
                    omask[obase + (long)j*HWD + xi*DD] = mv;
                }
            }
        }
    }
}

// ---------------------------------------------------------------------------
__global__ void mask_sum_kernel(const float* __restrict__ a1,
                                const float* __restrict__ a2) {
    int n = blockIdx.x * blockDim.x + threadIdx.x;
    if (n >= B_*HW) return;
    const float4* p1 = (const float4*)(a1 + (size_t)n * DD);
    const float4* p2 = (const float4*)(a2 + (size_t)n * DD);
    float4 u = p1[0], v = p1[1];
    float s1 = u.x+u.y+u.z+u.w + v.x+v.y+v.z+v.w;
    u = p2[0]; v = p2[1];
    float s2 = u.x+u.y+u.z+u.w + v.x+v.y+v.z+v.w;
    g_m1[n] = fminf(fmaxf(s1, 0.f), 1.f);
    g_m2[n] = fminf(fmaxf(s2, 0.f), 1.f);
}

// ---------------------------------------------------------------------------
extern "C" void kernel_launch(void* const* d_in, const int* in_sizes, int n_in,
                              void* d_out, int out_size) {
    const float* f1 = (const float*)d_in[0];
    const float* a1 = (const float*)d_in[1];
    const float* f2 = (const float*)d_in[2];
    const float* a2 = (const float*)d_in[3];
    float* out      = (float*)d_out;
    float* out_mask = out + (long)B_ * NIDX * HWD;

    mask_sum_kernel<<<(B_*HW + 255) / 256, 256>>>(a1, a2);

    dim3 g(W_ / PX, H_, B_);
    cost_kernel<<<g, 128, SMEM_BYTES>>>(f1, f2, out, out_mask);
}